// round 16
// baseline (speedup 1.0000x reference)
#include <cuda_runtime.h>
#include <cuda_fp16.h>
#include <math.h>
#include <stdint.h>

#define VOCAB 50000
#define EMB   300
#define SEQ   80
#define HID   128
#define BATCH 4096

typedef unsigned long long ull;

// Scratch: projected embedding table P = emb @ Wxh (25.6 MB, L2-resident at use)
__device__ float g_P[VOCAB * HID];

__device__ __forceinline__ uint32_t su32(const void* p) {
    uint32_t a;
    asm("{ .reg .u64 t; cvta.to.shared.u64 t, %1; cvt.u32.u64 %0, t; }" : "=r"(a) : "l"(p));
    return a;
}
__device__ __forceinline__ float ftanh(float x) {
    float e = __expf(2.f * x);
    return 1.f - __fdividef(2.f, e + 1.f);
}
__device__ __forceinline__ uint32_t pkh(float a, float b) {
    __half2 h = __halves2half2(__float2half_rn(a), __float2half_rn(b));
    return *reinterpret_cast<uint32_t*>(&h);
}

// ---------------------------------------------------------------------------
// Kernel A: P[v][j] = sum_e emb[v][e] * Wxh[e][j]
// (proven R4 SIMT version; added min-blocks=2 to guarantee dual residency)
// ---------------------------------------------------------------------------
#define PTK 20

__global__ __launch_bounds__(256, 2) void proj_kernel(const float* __restrict__ emb,
                                                      const float* __restrict__ Wxh) {
    __shared__ float As[2][PTK][128];
    __shared__ float Bs[2][PTK][128];

    const int tid = threadIdx.x;
    const int v0  = blockIdx.x * 128;
    const int tr  = tid >> 4;
    const int tc  = tid & 15;

    float acc[8][8];
#pragma unroll
    for (int i = 0; i < 8; i++)
#pragma unroll
        for (int j = 0; j < 8; j++) acc[i][j] = 0.f;

    const bool isA = (tid < 128);
    int av = v0 + tid; if (av > VOCAB - 1) av = VOCAB - 1;
    const int t2   = tid - 128;
    const int brow = t2 >> 5;
    const int bcol = (t2 & 31) * 4;

    float4 pf[5];
#pragma unroll
    for (int q = 0; q < 5; q++) {
        if (isA) pf[q] = *(const float4*)&emb[(long)av * EMB + 0 + q * 4];
        else     pf[q] = *(const float4*)&Wxh[(0 + q * 4 + brow) * HID + bcol];
    }

    for (int it = 0; it < 15; it++) {
        const int pb = it & 1;
        if (isA) {
#pragma unroll
            for (int q = 0; q < 5; q++) {
                As[pb][q * 4 + 0][tid] = pf[q].x;
                As[pb][q * 4 + 1][tid] = pf[q].y;
                As[pb][q * 4 + 2][tid] = pf[q].z;
                As[pb][q * 4 + 3][tid] = pf[q].w;
            }
        } else {
#pragma unroll
            for (int q = 0; q < 5; q++)
                *(float4*)&Bs[pb][q * 4 + brow][bcol] = pf[q];
        }
        __syncthreads();

        if (it + 1 < 15) {
            const int e0 = (it + 1) * PTK;
#pragma unroll
            for (int q = 0; q < 5; q++) {
                if (isA) pf[q] = *(const float4*)&emb[(long)av * EMB + e0 + q * 4];
                else     pf[q] = *(const float4*)&Wxh[(e0 + q * 4 + brow) * HID + bcol];
            }
        }

#pragma unroll
        for (int k = 0; k < PTK; k++) {
            float a[8], b[8];
            *(float4*)&a[0] = *(const float4*)&As[pb][k][tr * 8];
            *(float4*)&a[4] = *(const float4*)&As[pb][k][tr * 8 + 4];
            *(float4*)&b[0] = *(const float4*)&Bs[pb][k][tc * 8];
            *(float4*)&b[4] = *(const float4*)&Bs[pb][k][tc * 8 + 4];
#pragma unroll
            for (int i = 0; i < 8; i++)
#pragma unroll
                for (int j = 0; j < 8; j++) acc[i][j] += a[i] * b[j];
        }
        __syncthreads();
    }

#pragma unroll
    for (int i = 0; i < 8; i++) {
        const int v = v0 + tr * 8 + i;
        if (v < VOCAB) {
            *(float4*)&g_P[(long)v * HID + tc * 8]     = *(float4*)&acc[i][0];
            *(float4*)&g_P[(long)v * HID + tc * 8 + 4] = *(float4*)&acc[i][4];
        }
    }
}

// ---------------------------------------------------------------------------
// Kernel B: tensor-core recurrence. 16-row blocks (R15 addressing) with
// 4 WIDE warps (R11's proven 4-n-group mma body): 128 threads, warp wc=0..3
// owns cols wc*32..+31. Per warp per step: 16 ldmatrix + 96 HMMA + 16 tanh.
// Halves per-SM LDSM traffic vs R15 (A no longer fetched by 8 warps) and
// doubles independent mma chains per warp (4 n-groups).
// 2 blocks/SM (smem 70656 -> 141 KB; regs ~240 @128thr -> fits).
// ---------------------------------------------------------------------------
#define HPITCH 272          // bytes per h row (136 halves)
#define HSEG16 4352         // 16 rows * 272
// smem: [0,17408) h bufs: b0_hi@0 b0_lo@4352 b1_hi@8704 b1_lo@13056
//       [17408,17664) red[16][4]
//       [65536,70656) tok  (Whh fp32 occupies [0,65536) during init only)

__global__ __launch_bounds__(128, 2) void rnn_tc_kernel(const int* __restrict__ x,
                                                        const float* __restrict__ Whh,
                                                        const float* __restrict__ bh,
                                                        const float* __restrict__ Wd,
                                                        const float* __restrict__ bd,
                                                        float* __restrict__ out) {
    extern __shared__ char smc[];
    float* Whh_sh = (float*)smc;
    int*   tok_sh = (int*)(smc + 65536);
    char*  hbase  = smc;
    float* red    = (float*)(smc + 17408);   // 16 rows x 4 wc

    const int tid  = threadIdx.x;
    const int lane = tid & 31;
    const int wc   = tid >> 5;       // 0..3 col group (32 cols)
    const int g    = lane >> 2;
    const int q    = lane & 3;
    const int b0   = blockIdx.x * 16;

    // ---- init: Whh fp32 + tokens ----
    {
        const float4* s = (const float4*)Whh;
        float4* d = (float4*)Whh_sh;
        for (int i = tid; i < HID * HID / 4; i += 128) d[i] = s[i];
        const int4* xs = (const int4*)(x + b0 * SEQ);
        int4* td = (int4*)tok_sh;
        for (int i = tid; i < 16 * SEQ / 4; i += 128) td[i] = xs[i];
    }
    __syncthreads();

    // ---- extract B fragments (hi/lo) into registers (R11 verbatim) ----
    uint32_t Bh[8][4][2], Bl[8][4][2];
#pragma unroll
    for (int s = 0; s < 8; s++) {
        const int k0 = s * 16 + 2 * q;
#pragma unroll
        for (int n = 0; n < 4; n++) {
            const int nc = wc * 32 + n * 8 + g;
            float w00 = Whh_sh[(k0)     * HID + nc];
            float w01 = Whh_sh[(k0 + 1) * HID + nc];
            float w10 = Whh_sh[(k0 + 8) * HID + nc];
            float w11 = Whh_sh[(k0 + 9) * HID + nc];
            float h00 = __half2float(__float2half_rn(w00));
            float h01 = __half2float(__float2half_rn(w01));
            float h10 = __half2float(__float2half_rn(w10));
            float h11 = __half2float(__float2half_rn(w11));
            Bh[s][n][0] = pkh(h00, h01);
            Bh[s][n][1] = pkh(h10, h11);
            Bl[s][n][0] = pkh(w00 - h00, w01 - h01);
            Bl[s][n][1] = pkh(w10 - h10, w11 - h11);
        }
    }
    __syncthreads();   // Whh_sh region now free for h buffers

    float2 bh2[4];
#pragma unroll
    for (int n = 0; n < 4; n++)
        bh2[n] = *(const float2*)&bh[wc * 32 + n * 8 + 2 * q];

    const int rowA = g;              // 0..7
    const int rowB = g + 8;          // 8..15
    const uint32_t smem_u32 = su32(smc);
    const uint32_t lm_off = (uint32_t)((lane & 15) * HPITCH + (lane >> 4) * 16);
    uint32_t stA[4], stB[4];
#pragma unroll
    for (int n = 0; n < 4; n++) {
        const int col = wc * 32 + n * 8 + 2 * q;
        stA[n] = (uint32_t)(rowA * HPITCH + col * 2);
        stB[n] = (uint32_t)(rowB * HPITCH + col * 2);
    }

    // prefetch t=0 inputs
    float2 xp[2][4];
    {
        const int tkA = tok_sh[rowA * SEQ + 0];
        const int tkB = tok_sh[rowB * SEQ + 0];
#pragma unroll
        for (int n = 0; n < 4; n++) {
            xp[0][n] = *(const float2*)&g_P[tkA * HID + wc * 32 + n * 8 + 2 * q];
            xp[1][n] = *(const float2*)&g_P[tkB * HID + wc * 32 + n * 8 + 2 * q];
        }
    }

    float v[4][4];   // tanh values, persist to epilogue

    for (int t = 0; t < SEQ; t++) {
        float acc[4][4];
#pragma unroll
        for (int n = 0; n < 4; n++) {
            acc[n][0] = xp[0][n].x + bh2[n].x;
            acc[n][1] = xp[0][n].y + bh2[n].y;
            acc[n][2] = xp[1][n].x + bh2[n].x;
            acc[n][3] = xp[1][n].y + bh2[n].y;
        }

        if (t + 1 < SEQ) {
            const int tkA = tok_sh[rowA * SEQ + t + 1];
            const int tkB = tok_sh[rowB * SEQ + t + 1];
#pragma unroll
            for (int n = 0; n < 4; n++) {
                xp[0][n] = *(const float2*)&g_P[tkA * HID + wc * 32 + n * 8 + 2 * q];
                xp[1][n] = *(const float2*)&g_P[tkB * HID + wc * 32 + n * 8 + 2 * q];
            }
        }

        if (t > 0) {
            const uint32_t hseg = smem_u32 + ((t + 1) & 1) * (2 * HSEG16);
#pragma unroll
            for (int s = 0; s < 8; s++) {
                uint32_t Ah[4], Al[4];
                asm volatile("ldmatrix.sync.aligned.m8n8.x4.shared.b16 {%0,%1,%2,%3}, [%4];"
                             : "=r"(Ah[0]), "=r"(Ah[1]), "=r"(Ah[2]), "=r"(Ah[3])
                             : "r"(hseg + lm_off + s * 32));
                asm volatile("ldmatrix.sync.aligned.m8n8.x4.shared.b16 {%0,%1,%2,%3}, [%4];"
                             : "=r"(Al[0]), "=r"(Al[1]), "=r"(Al[2]), "=r"(Al[3])
                             : "r"(hseg + HSEG16 + lm_off + s * 32));
#pragma unroll
                for (int n = 0; n < 4; n++) {
                    asm volatile(
                        "mma.sync.aligned.m16n8k16.row.col.f32.f16.f16.f32 "
                        "{%0,%1,%2,%3}, {%4,%5,%6,%7}, {%8,%9}, {%0,%1,%2,%3};"
                        : "+f"(acc[n][0]), "+f"(acc[n][1]), "+f"(acc[n][2]), "+f"(acc[n][3])
                        : "r"(Ah[0]), "r"(Ah[1]), "r"(Ah[2]), "r"(Ah[3]),
                          "r"(Bh[s][n][0]), "r"(Bh[s][n][1]));
                    asm volatile(
                        "mma.sync.aligned.m16n8k16.row.col.f32.f16.f16.f32 "
                        "{%0,%1,%2,%3}, {%4,%5,%6,%7}, {%8,%9}, {%0,%1,%2,%3};"
                        : "+f"(acc[n][0]), "+f"(acc[n][1]), "+f"(acc[n][2]), "+f"(acc[n][3])
                        : "r"(Ah[0]), "r"(Ah[1]), "r"(Ah[2]), "r"(Ah[3]),
                          "r"(Bl[s][n][0]), "r"(Bl[s][n][1]));
                    asm volatile(
                        "mma.sync.aligned.m16n8k16.row.col.f32.f16.f16.f32 "
                        "{%0,%1,%2,%3}, {%4,%5,%6,%7}, {%8,%9}, {%0,%1,%2,%3};"
                        : "+f"(acc[n][0]), "+f"(acc[n][1]), "+f"(acc[n][2]), "+f"(acc[n][3])
                        : "r"(Al[0]), "r"(Al[1]), "r"(Al[2]), "r"(Al[3]),
                          "r"(Bh[s][n][0]), "r"(Bh[s][n][1]));
                }
            }
        }

        // tanh
#pragma unroll
        for (int n = 0; n < 4; n++)
#pragma unroll
            for (int d = 0; d < 4; d++)
                v[n][d] = ftanh(acc[n][d]);

        // store h(t) hi/lo to buf t&1
        {
            char* ws = hbase + (t & 1) * (2 * HSEG16);
#pragma unroll
            for (int n = 0; n < 4; n++) {
                float h0 = __half2float(__float2half_rn(v[n][0]));
                float h1 = __half2float(__float2half_rn(v[n][1]));
                float h2 = __half2float(__float2half_rn(v[n][2]));
                float h3 = __half2float(__float2half_rn(v[n][3]));
                *(uint32_t*)(ws + stA[n])          = pkh(h0, h1);
                *(uint32_t*)(ws + HSEG16 + stA[n]) = pkh(v[n][0] - h0, v[n][1] - h1);
                *(uint32_t*)(ws + stB[n])          = pkh(h2, h3);
                *(uint32_t*)(ws + HSEG16 + stB[n]) = pkh(v[n][2] - h2, v[n][3] - h3);
            }
        }
        __syncthreads();
    }

    // ---- Dense(1) + sigmoid ----
    float pA = 0.f, pB = 0.f;
#pragma unroll
    for (int n = 0; n < 4; n++) {
        const float2 wd2 = *(const float2*)&Wd[wc * 32 + n * 8 + 2 * q];
        pA += v[n][0] * wd2.x + v[n][1] * wd2.y;
        pB += v[n][2] * wd2.x + v[n][3] * wd2.y;
    }
    pA += __shfl_xor_sync(0xffffffff, pA, 1);
    pA += __shfl_xor_sync(0xffffffff, pA, 2);
    pB += __shfl_xor_sync(0xffffffff, pB, 1);
    pB += __shfl_xor_sync(0xffffffff, pB, 2);
    if (q == 0) {
        red[rowA * 4 + wc] = pA;
        red[rowB * 4 + wc] = pB;
    }
    __syncthreads();
    if (tid < 16) {
        float s = bd[0];
#pragma unroll
        for (int c = 0; c < 4; c++) s += red[tid * 4 + c];
        out[b0 + tid] = __fdividef(1.f, 1.f + __expf(-s));
    }
}

// ---------------------------------------------------------------------------
extern "C" void kernel_launch(void* const* d_in, const int* in_sizes, int n_in,
                              void* d_out, int out_size) {
    const int*   x   = (const int*)d_in[0];
    const float* emb = (const float*)d_in[1];
    const float* Wxh = (const float*)d_in[2];
    const float* Whh = (const float*)d_in[3];
    const float* bh  = (const float*)d_in[4];
    const float* Wd  = (const float*)d_in[5];
    const float* bd  = (const float*)d_in[6];
    float* out = (float*)d_out;

    proj_kernel<<<(VOCAB + 127) / 128, 256>>>(emb, Wxh);

    const int smem = 65536 + 16 * SEQ * 4;   // 70656 B -> 2 blocks/SM
    cudaFuncSetAttribute(rnn_tc_kernel, cudaFuncAttributeMaxDynamicSharedMemorySize, smem);
    rnn_tc_kernel<<<BATCH / 16, 128, smem>>>(x, Whh, bh, Wd, bd, out);
}

// round 17
// speedup vs baseline: 1.0888x; 1.0888x over previous
#include <cuda_runtime.h>
#include <cuda_fp16.h>
#include <math.h>
#include <stdint.h>

#define VOCAB 50000
#define EMB   300
#define SEQ   80
#define HID   128
#define BATCH 4096

typedef unsigned long long ull;

// Scratch: projected embedding table P = emb @ Wxh (25.6 MB, L2-resident at use)
__device__ float g_P[VOCAB * HID];

__device__ __forceinline__ uint32_t su32(const void* p) {
    uint32_t a;
    asm("{ .reg .u64 t; cvta.to.shared.u64 t, %1; cvt.u32.u64 %0, t; }" : "=r"(a) : "l"(p));
    return a;
}
__device__ __forceinline__ float ftanh(float x) {
    float e = __expf(2.f * x);
    return 1.f - __fdividef(2.f, e + 1.f);
}
__device__ __forceinline__ uint32_t pkh(float a, float b) {
    __half2 h = __halves2half2(__float2half_rn(a), __float2half_rn(b));
    return *reinterpret_cast<uint32_t*>(&h);
}

// ---------------------------------------------------------------------------
// Kernel A: P[v][j] = sum_e emb[v][e] * Wxh[e][j]
// EXACT R4/R11 proven version (measured ~107us): PTK=20, double-buffered,
// 1 sync/iter, grid=391, NO min-blocks bound (needs >128 regs; bounding to
// 2 blocks spills the 8x8 accumulator tile — measured +27us in R16).
// ---------------------------------------------------------------------------
#define PTK 20

__global__ __launch_bounds__(256) void proj_kernel(const float* __restrict__ emb,
                                                   const float* __restrict__ Wxh) {
    __shared__ float As[2][PTK][128];
    __shared__ float Bs[2][PTK][128];

    const int tid = threadIdx.x;
    const int v0  = blockIdx.x * 128;
    const int tr  = tid >> 4;
    const int tc  = tid & 15;

    float acc[8][8];
#pragma unroll
    for (int i = 0; i < 8; i++)
#pragma unroll
        for (int j = 0; j < 8; j++) acc[i][j] = 0.f;

    const bool isA = (tid < 128);
    int av = v0 + tid; if (av > VOCAB - 1) av = VOCAB - 1;
    const int t2   = tid - 128;
    const int brow = t2 >> 5;
    const int bcol = (t2 & 31) * 4;

    float4 pf[5];
#pragma unroll
    for (int q = 0; q < 5; q++) {
        if (isA) pf[q] = *(const float4*)&emb[(long)av * EMB + 0 + q * 4];
        else     pf[q] = *(const float4*)&Wxh[(0 + q * 4 + brow) * HID + bcol];
    }

    for (int it = 0; it < 15; it++) {
        const int pb = it & 1;
        if (isA) {
#pragma unroll
            for (int q = 0; q < 5; q++) {
                As[pb][q * 4 + 0][tid] = pf[q].x;
                As[pb][q * 4 + 1][tid] = pf[q].y;
                As[pb][q * 4 + 2][tid] = pf[q].z;
                As[pb][q * 4 + 3][tid] = pf[q].w;
            }
        } else {
#pragma unroll
            for (int q = 0; q < 5; q++)
                *(float4*)&Bs[pb][q * 4 + brow][bcol] = pf[q];
        }
        __syncthreads();

        if (it + 1 < 15) {
            const int e0 = (it + 1) * PTK;
#pragma unroll
            for (int q = 0; q < 5; q++) {
                if (isA) pf[q] = *(const float4*)&emb[(long)av * EMB + e0 + q * 4];
                else     pf[q] = *(const float4*)&Wxh[(e0 + q * 4 + brow) * HID + bcol];
            }
        }

#pragma unroll
        for (int k = 0; k < PTK; k++) {
            float a[8], b[8];
            *(float4*)&a[0] = *(const float4*)&As[pb][k][tr * 8];
            *(float4*)&a[4] = *(const float4*)&As[pb][k][tr * 8 + 4];
            *(float4*)&b[0] = *(const float4*)&Bs[pb][k][tc * 8];
            *(float4*)&b[4] = *(const float4*)&Bs[pb][k][tc * 8 + 4];
#pragma unroll
            for (int i = 0; i < 8; i++)
#pragma unroll
                for (int j = 0; j < 8; j++) acc[i][j] += a[i] * b[j];
        }
        __syncthreads();
    }

#pragma unroll
    for (int i = 0; i < 8; i++) {
        const int v = v0 + tr * 8 + i;
        if (v < VOCAB) {
            *(float4*)&g_P[(long)v * HID + tc * 8]     = *(float4*)&acc[i][0];
            *(float4*)&g_P[(long)v * HID + tc * 8 + 4] = *(float4*)&acc[i][4];
        }
    }
}

// ---------------------------------------------------------------------------
// Kernel B: tensor-core recurrence — EXACT R16 version (measured 118.8us).
// 16-row blocks, 128 threads = 4 wide warps (warp wc owns cols wc*32..+31),
// 2 blocks/SM (separate barrier domains overlap mma with tanh/store).
// Per warp per step: 16 ldmatrix + 96 HMMA + 16 tanh.
// ---------------------------------------------------------------------------
#define HPITCH 272          // bytes per h row (136 halves)
#define HSEG16 4352         // 16 rows * 272
// smem: [0,17408) h bufs: b0_hi@0 b0_lo@4352 b1_hi@8704 b1_lo@13056
//       [17408,17664) red[16][4]
//       [65536,70656) tok  (Whh fp32 occupies [0,65536) during init only)

__global__ __launch_bounds__(128, 2) void rnn_tc_kernel(const int* __restrict__ x,
                                                        const float* __restrict__ Whh,
                                                        const float* __restrict__ bh,
                                                        const float* __restrict__ Wd,
                                                        const float* __restrict__ bd,
                                                        float* __restrict__ out) {
    extern __shared__ char smc[];
    float* Whh_sh = (float*)smc;
    int*   tok_sh = (int*)(smc + 65536);
    char*  hbase  = smc;
    float* red    = (float*)(smc + 17408);   // 16 rows x 4 wc

    const int tid  = threadIdx.x;
    const int lane = tid & 31;
    const int wc   = tid >> 5;       // 0..3 col group (32 cols)
    const int g    = lane >> 2;
    const int q    = lane & 3;
    const int b0   = blockIdx.x * 16;

    // ---- init: Whh fp32 + tokens ----
    {
        const float4* s = (const float4*)Whh;
        float4* d = (float4*)Whh_sh;
        for (int i = tid; i < HID * HID / 4; i += 128) d[i] = s[i];
        const int4* xs = (const int4*)(x + b0 * SEQ);
        int4* td = (int4*)tok_sh;
        for (int i = tid; i < 16 * SEQ / 4; i += 128) td[i] = xs[i];
    }
    __syncthreads();

    // ---- extract B fragments (hi/lo) into registers ----
    uint32_t Bh[8][4][2], Bl[8][4][2];
#pragma unroll
    for (int s = 0; s < 8; s++) {
        const int k0 = s * 16 + 2 * q;
#pragma unroll
        for (int n = 0; n < 4; n++) {
            const int nc = wc * 32 + n * 8 + g;
            float w00 = Whh_sh[(k0)     * HID + nc];
            float w01 = Whh_sh[(k0 + 1) * HID + nc];
            float w10 = Whh_sh[(k0 + 8) * HID + nc];
            float w11 = Whh_sh[(k0 + 9) * HID + nc];
            float h00 = __half2float(__float2half_rn(w00));
            float h01 = __half2float(__float2half_rn(w01));
            float h10 = __half2float(__float2half_rn(w10));
            float h11 = __half2float(__float2half_rn(w11));
            Bh[s][n][0] = pkh(h00, h01);
            Bh[s][n][1] = pkh(h10, h11);
            Bl[s][n][0] = pkh(w00 - h00, w01 - h01);
            Bl[s][n][1] = pkh(w10 - h10, w11 - h11);
        }
    }
    __syncthreads();   // Whh_sh region now free for h buffers

    float2 bh2[4];
#pragma unroll
    for (int n = 0; n < 4; n++)
        bh2[n] = *(const float2*)&bh[wc * 32 + n * 8 + 2 * q];

    const int rowA = g;              // 0..7
    const int rowB = g + 8;          // 8..15
    const uint32_t smem_u32 = su32(smc);
    const uint32_t lm_off = (uint32_t)((lane & 15) * HPITCH + (lane >> 4) * 16);
    uint32_t stA[4], stB[4];
#pragma unroll
    for (int n = 0; n < 4; n++) {
        const int col = wc * 32 + n * 8 + 2 * q;
        stA[n] = (uint32_t)(rowA * HPITCH + col * 2);
        stB[n] = (uint32_t)(rowB * HPITCH + col * 2);
    }

    // prefetch t=0 inputs
    float2 xp[2][4];
    {
        const int tkA = tok_sh[rowA * SEQ + 0];
        const int tkB = tok_sh[rowB * SEQ + 0];
#pragma unroll
        for (int n = 0; n < 4; n++) {
            xp[0][n] = *(const float2*)&g_P[tkA * HID + wc * 32 + n * 8 + 2 * q];
            xp[1][n] = *(const float2*)&g_P[tkB * HID + wc * 32 + n * 8 + 2 * q];
        }
    }

    float v[4][4];   // tanh values, persist to epilogue

    for (int t = 0; t < SEQ; t++) {
        float acc[4][4];
#pragma unroll
        for (int n = 0; n < 4; n++) {
            acc[n][0] = xp[0][n].x + bh2[n].x;
            acc[n][1] = xp[0][n].y + bh2[n].y;
            acc[n][2] = xp[1][n].x + bh2[n].x;
            acc[n][3] = xp[1][n].y + bh2[n].y;
        }

        if (t + 1 < SEQ) {
            const int tkA = tok_sh[rowA * SEQ + t + 1];
            const int tkB = tok_sh[rowB * SEQ + t + 1];
#pragma unroll
            for (int n = 0; n < 4; n++) {
                xp[0][n] = *(const float2*)&g_P[tkA * HID + wc * 32 + n * 8 + 2 * q];
                xp[1][n] = *(const float2*)&g_P[tkB * HID + wc * 32 + n * 8 + 2 * q];
            }
        }

        if (t > 0) {
            const uint32_t hseg = smem_u32 + ((t + 1) & 1) * (2 * HSEG16);
#pragma unroll
            for (int s = 0; s < 8; s++) {
                uint32_t Ah[4], Al[4];
                asm volatile("ldmatrix.sync.aligned.m8n8.x4.shared.b16 {%0,%1,%2,%3}, [%4];"
                             : "=r"(Ah[0]), "=r"(Ah[1]), "=r"(Ah[2]), "=r"(Ah[3])
                             : "r"(hseg + lm_off + s * 32));
                asm volatile("ldmatrix.sync.aligned.m8n8.x4.shared.b16 {%0,%1,%2,%3}, [%4];"
                             : "=r"(Al[0]), "=r"(Al[1]), "=r"(Al[2]), "=r"(Al[3])
                             : "r"(hseg + HSEG16 + lm_off + s * 32));
#pragma unroll
                for (int n = 0; n < 4; n++) {
                    asm volatile(
                        "mma.sync.aligned.m16n8k16.row.col.f32.f16.f16.f32 "
                        "{%0,%1,%2,%3}, {%4,%5,%6,%7}, {%8,%9}, {%0,%1,%2,%3};"
                        : "+f"(acc[n][0]), "+f"(acc[n][1]), "+f"(acc[n][2]), "+f"(acc[n][3])
                        : "r"(Ah[0]), "r"(Ah[1]), "r"(Ah[2]), "r"(Ah[3]),
                          "r"(Bh[s][n][0]), "r"(Bh[s][n][1]));
                    asm volatile(
                        "mma.sync.aligned.m16n8k16.row.col.f32.f16.f16.f32 "
                        "{%0,%1,%2,%3}, {%4,%5,%6,%7}, {%8,%9}, {%0,%1,%2,%3};"
                        : "+f"(acc[n][0]), "+f"(acc[n][1]), "+f"(acc[n][2]), "+f"(acc[n][3])
                        : "r"(Ah[0]), "r"(Ah[1]), "r"(Ah[2]), "r"(Ah[3]),
                          "r"(Bl[s][n][0]), "r"(Bl[s][n][1]));
                    asm volatile(
                        "mma.sync.aligned.m16n8k16.row.col.f32.f16.f16.f32 "
                        "{%0,%1,%2,%3}, {%4,%5,%6,%7}, {%8,%9}, {%0,%1,%2,%3};"
                        : "+f"(acc[n][0]), "+f"(acc[n][1]), "+f"(acc[n][2]), "+f"(acc[n][3])
                        : "r"(Al[0]), "r"(Al[1]), "r"(Al[2]), "r"(Al[3]),
                          "r"(Bh[s][n][0]), "r"(Bh[s][n][1]));
                }
            }
        }

        // tanh
#pragma unroll
        for (int n = 0; n < 4; n++)
#pragma unroll
            for (int d = 0; d < 4; d++)
                v[n][d] = ftanh(acc[n][d]);

        // store h(t) hi/lo to buf t&1
        {
            char* ws = hbase + (t & 1) * (2 * HSEG16);
#pragma unroll
            for (int n = 0; n < 4; n++) {
                float h0 = __half2float(__float2half_rn(v[n][0]));
                float h1 = __half2float(__float2half_rn(v[n][1]));
                float h2 = __half2float(__float2half_rn(v[n][2]));
                float h3 = __half2float(__float2half_rn(v[n][3]));
                *(uint32_t*)(ws + stA[n])          = pkh(h0, h1);
                *(uint32_t*)(ws + HSEG16 + stA[n]) = pkh(v[n][0] - h0, v[n][1] - h1);
                *(uint32_t*)(ws + stB[n])          = pkh(h2, h3);
                *(uint32_t*)(ws + HSEG16 + stB[n]) = pkh(v[n][2] - h2, v[n][3] - h3);
            }
        }
        __syncthreads();
    }

    // ---- Dense(1) + sigmoid ----
    float pA = 0.f, pB = 0.f;
#pragma unroll
    for (int n = 0; n < 4; n++) {
        const float2 wd2 = *(const float2*)&Wd[wc * 32 + n * 8 + 2 * q];
        pA += v[n][0] * wd2.x + v[n][1] * wd2.y;
        pB += v[n][2] * wd2.x + v[n][3] * wd2.y;
    }
    pA += __shfl_xor_sync(0xffffffff, pA, 1);
    pA += __shfl_xor_sync(0xffffffff, pA, 2);
    pB += __shfl_xor_sync(0xffffffff, pB, 1);
    pB += __shfl_xor_sync(0xffffffff, pB, 2);
    if (q == 0) {
        red[rowA * 4 + wc] = pA;
        red[rowB * 4 + wc] = pB;
    }
    __syncthreads();
    if (tid < 16) {
        float s = bd[0];
#pragma unroll
        for (int c = 0; c < 4; c++) s += red[tid * 4 + c];
        out[b0 + tid] = __fdividef(1.f, 1.f + __expf(-s));
    }
}

// ---------------------------------------------------------------------------
extern "C" void kernel_launch(void* const* d_in, const int* in_sizes, int n_in,
                              void* d_out, int out_size) {
    const int*   x   = (const int*)d_in[0];
    const float* emb = (const float*)d_in[1];
    const float* Wxh = (const float*)d_in[2];
    const float* Whh = (const float*)d_in[3];
    const float* bh  = (const float*)d_in[4];
    const float* Wd  = (const float*)d_in[5];
    const float* bd  = (const float*)d_in[6];
    float* out = (float*)d_out;

    proj_kernel<<<(VOCAB + 127) / 128, 256>>>(emb, Wxh);

    const int smem = 65536 + 16 * SEQ * 4;   // 70656 B -> 2 blocks/SM
    cudaFuncSetAttribute(rnn_tc_kernel, cudaFuncAttributeMaxDynamicSharedMemorySize, smem);
    rnn_tc_kernel<<<BATCH / 16, 128, smem>>>(x, Whh, bh, Wd, bd, out);
}